// round 4
// baseline (speedup 1.0000x reference)
#include <cuda_runtime.h>
#include <math.h>

// Problem constants
#define NN 128      // memory slots
#define MM 64       // memory width
#define CTRL 512
#define NO 70       // M + 6 controller outputs
#define BMAX 16384
#define EPSF 1e-16f

// Scratch for controller outputs o = emb @ W^T + b  (B x 70)
__device__ float g_o[BMAX * NO];

// ---------------------------------------------------------------------------
// Kernel 1: tiled GEMM  O[B,70] = A[B,512] * W[70,512]^T + bias
// BM=64 (grid 256), BK=32, 256 threads, per-thread 2x9 tile, double-buffered.
// ---------------------------------------------------------------------------
__global__ __launch_bounds__(256) void ntm_gemm_kernel(
    const float* __restrict__ A,     // [B,512]
    const float* __restrict__ W,     // [70,512]
    const float* __restrict__ bias)  // [70]
{
    // [buf][kk][r]: stride 65 -> store banks (kk + r) % 32 conflict-free
    __shared__ float As[2][32][65];
    // [buf][kk][c]: stride 73 -> store banks (9*kk + c) % 32 conflict-free
    __shared__ float Ws[2][32][73];

    const int t = threadIdx.x;
    const int block_row = blockIdx.x * 64;
    const int tcol = t & 7;        // 8 col groups * 9 cols = 72
    const int trow = t >> 3;       // 32 row groups * 2 rows = 64

    float acc[2][9];
#pragma unroll
    for (int i = 0; i < 2; i++)
#pragma unroll
        for (int j = 0; j < 9; j++) acc[i][j] = 0.f;

    float4 a_ld[2];
    float4 w_ld[3];

    // ---- staging helpers (as macros so regs stay in scope) ----
#define LOAD_TILE(k0)                                                         \
    {                                                                         \
        _Pragma("unroll")                                                     \
        for (int i = 0; i < 2; i++) {                                         \
            int lin = t + 256 * i;           /* 0..511 */                     \
            int r = lin >> 3, c4 = lin & 7;                                   \
            a_ld[i] = *(const float4*)&A[(size_t)(block_row + r) * CTRL +     \
                                         (k0) + 4 * c4];                      \
        }                                                                     \
        _Pragma("unroll")                                                     \
        for (int i = 0; i < 3; i++) {                                         \
            int lin = t + 256 * i;           /* 0..767, valid < 576 */       \
            int c = lin >> 3, c4 = lin & 7;                                   \
            if (lin < 576)                                                    \
                w_ld[i] = (c < NO)                                            \
                    ? *(const float4*)&W[(size_t)c * CTRL + (k0) + 4 * c4]    \
                    : make_float4(0.f, 0.f, 0.f, 0.f);                        \
        }                                                                     \
    }

#define STORE_TILE(buf)                                                       \
    {                                                                         \
        _Pragma("unroll")                                                     \
        for (int i = 0; i < 2; i++) {                                         \
            int lin = t + 256 * i;                                            \
            int r = lin >> 3, c4 = lin & 7;                                   \
            As[buf][4 * c4 + 0][r] = a_ld[i].x;                               \
            As[buf][4 * c4 + 1][r] = a_ld[i].y;                               \
            As[buf][4 * c4 + 2][r] = a_ld[i].z;                               \
            As[buf][4 * c4 + 3][r] = a_ld[i].w;                               \
        }                                                                     \
        _Pragma("unroll")                                                     \
        for (int i = 0; i < 3; i++) {                                         \
            int lin = t + 256 * i;                                            \
            int c = lin >> 3, c4 = lin & 7;                                   \
            if (lin < 576) {                                                  \
                Ws[buf][4 * c4 + 0][c] = w_ld[i].x;                           \
                Ws[buf][4 * c4 + 1][c] = w_ld[i].y;                           \
                Ws[buf][4 * c4 + 2][c] = w_ld[i].z;                           \
                Ws[buf][4 * c4 + 3][c] = w_ld[i].w;                           \
            }                                                                 \
        }                                                                     \
    }

    LOAD_TILE(0);
    STORE_TILE(0);
    __syncthreads();

#pragma unroll 1
    for (int tile = 0; tile < 16; tile++) {
        const int buf = tile & 1;
        if (tile < 15) LOAD_TILE((tile + 1) * 32);   // prefetch into regs

#pragma unroll
        for (int kk = 0; kk < 32; kk++) {
            float a0 = As[buf][kk][trow * 2 + 0];
            float a1 = As[buf][kk][trow * 2 + 1];
            float wv[9];
#pragma unroll
            for (int j = 0; j < 9; j++) wv[j] = Ws[buf][kk][tcol * 9 + j];
#pragma unroll
            for (int j = 0; j < 9; j++) {
                acc[0][j] += a0 * wv[j];
                acc[1][j] += a1 * wv[j];
            }
        }

        if (tile < 15) STORE_TILE(buf ^ 1);
        __syncthreads();
    }

#pragma unroll
    for (int i = 0; i < 2; i++) {
        int row = block_row + trow * 2 + i;
#pragma unroll
        for (int j = 0; j < 9; j++) {
            int c = tcol * 9 + j;
            if (c < NO) g_o[(size_t)row * NO + c] = acc[i][j] + bias[c];
        }
    }
#undef LOAD_TILE
#undef STORE_TILE
}

// ---------------------------------------------------------------------------
// Kernel 2: addressing + readout. One block per batch row, 128 threads.
// No SMEM tile: dot pass reads rows from global; readout re-reads via L2.
// ---------------------------------------------------------------------------
__device__ __forceinline__ float softplus_f(float x) {
    return (x > 20.f) ? x : log1pf(expf(x));
}

__device__ __forceinline__ float warp_sum(float v) {
#pragma unroll
    for (int off = 16; off > 0; off >>= 1)
        v += __shfl_xor_sync(0xffffffffu, v, off);
    return v;
}
__device__ __forceinline__ float warp_max(float v) {
#pragma unroll
    for (int off = 16; off > 0; off >>= 1)
        v = fmaxf(v, __shfl_xor_sync(0xffffffffu, v, off));
    return v;
}

__global__ __launch_bounds__(128, 8) void ntm_addr_kernel(
    const float* __restrict__ w_prev,  // [B,128]
    const float* __restrict__ memory,  // [B,128,64]
    float* __restrict__ out_r,         // [B,64]
    float* __restrict__ out_w)         // [B,128]
{
    __shared__ float ke[MM];           // k + EPS
    __shared__ float wg[NN];           // w_g, later reused for final w
    __shared__ float rq[8 * MM];       // readout partials: 8 groups x 64 cols
    __shared__ float red[8];
    __shared__ float scal[8];          // beta,g,s0,s1,s2,gamma,inv_knorm

    const int b = blockIdx.x;
    const int t = threadIdx.x;
    const int wid = t >> 5;
    const int lane = t & 31;

    const float* ob = g_o + (size_t)b * NO;

    // hoist w_prev load (independent of everything until interpolation)
    const float wp = w_prev[(size_t)b * NN + t];

    // --- scalars + k ---
    if (t < MM) {
        ke[t] = ob[t] + EPSF;
    } else if (t == 64) {
        scal[0] = softplus_f(ob[MM]);                       // beta
    } else if (t == 65) {
        scal[1] = 1.f / (1.f + expf(-ob[MM + 1]));          // g
    } else if (t == 66) {
        float a = ob[MM + 2], bb = ob[MM + 3], c = ob[MM + 4];
        float mx = fmaxf(a, fmaxf(bb, c));
        float e0 = expf(a - mx), e1 = expf(bb - mx), e2 = expf(c - mx);
        float inv = 1.f / (e0 + e1 + e2);
        scal[2] = e0 * inv; scal[3] = e1 * inv; scal[4] = e2 * inv;   // s
    } else if (t == 67) {
        scal[5] = 1.f + softplus_f(ob[MM + 5]);             // gamma
    }
    __syncthreads();   // ke + scalars visible

    // --- k norm (warp 0, overlaps with other warps starting the dot) ---
    if (t < 32) {
        float v = ke[t] * ke[t] + ke[t + 32] * ke[t + 32];
        v = warp_sum(v);
        if (t == 0) scal[6] = rsqrtf(v);    // 1/||k||
    }

    // --- cosine similarity: thread t owns row n = t, straight from global ---
    const float4* mrow = (const float4*)(memory + (size_t)b * NN * MM) + t * 16;
    const float4* k4 = (const float4*)ke;
    float d = 0.f, q = 0.f;
#pragma unroll
    for (int i = 0; i < 16; i++) {
        float4 v = mrow[i];
        float4 kv = k4[i];
        d += v.x * kv.x; q += v.x * v.x;
        d += v.y * kv.y; q += v.y * v.y;
        d += v.z * kv.z; q += v.z * v.z;
        d += v.w * kv.w; q += v.w * v.w;
    }
    __syncthreads();   // scal[6] visible

    const float beta = scal[0], g = scal[1];
    const float s0 = scal[2], s1 = scal[3], s2 = scal[4];
    const float gamma = scal[5];

    float cosv = d * rsqrtf(q) * scal[6];
    float z = beta * cosv;

    // --- softmax over 128 slots ---
    float mx = warp_max(z);
    if (lane == 0) red[wid] = mx;
    __syncthreads();
    mx = fmaxf(fmaxf(red[0], red[1]), fmaxf(red[2], red[3]));
    float e = expf(z - mx);
    float sw = warp_sum(e);
    if (lane == 0) red[4 + wid] = sw;
    __syncthreads();
    float inv_sum = 1.f / (red[4] + red[5] + red[6] + red[7]);
    float wc = e * inv_sum;

    // --- interpolate with previous weights ---
    float wgv = g * wc + (1.f - g) * wp;
    wg[t] = wgv;
    __syncthreads();

    // --- circular shift ---
    float ws = s0 * wg[(t + NN - 1) & (NN - 1)]
             + s1 * wgv
             + s2 * wg[(t + 1) & (NN - 1)];

    // --- sharpen + normalize ---
    float wsh = powf(ws, gamma);
    float ssum = warp_sum(wsh);
    if (lane == 0) red[wid] = ssum;
    __syncthreads();            // also guarantees wg reads above are done
    float wfin = wsh / ((red[0] + red[1] + red[2] + red[3]) + EPSF);
    out_w[(size_t)b * NN + t] = wfin;
    wg[t] = wfin;               // reuse for readout broadcast
    __syncthreads();

    // --- readout r[m] = sum_n w[n] * mem[n][m], coalesced re-read via L2 ---
    // thread: mc = float4-column (0..15), grp = n-sixteenth (0..7)
    const int mc = t & 15;
    const int grp = t >> 4;
    const int n0 = grp * 16;
    const float4* mcol = (const float4*)(memory + (size_t)b * NN * MM);
    float4 acc = make_float4(0.f, 0.f, 0.f, 0.f);
#pragma unroll
    for (int j = 0; j < 16; j++) {
        float wv = wg[n0 + j];
        float4 v = mcol[(size_t)(n0 + j) * 16 + mc];
        acc.x += wv * v.x; acc.y += wv * v.y;
        acc.z += wv * v.z; acc.w += wv * v.w;
    }
    ((float4*)rq)[grp * 16 + mc] = acc;
    __syncthreads();
    if (t < MM) {
        float s = 0.f;
#pragma unroll
        for (int gg = 0; gg < 8; gg++) s += rq[gg * MM + t];
        out_r[(size_t)b * MM + t] = s;
    }
}

// ---------------------------------------------------------------------------
// Launcher — exactly two kernel launches (graph-capture safe).
// ---------------------------------------------------------------------------
extern "C" void kernel_launch(void* const* d_in, const int* in_sizes, int n_in,
                              void* d_out, int out_size)
{
    const float* embeddings = (const float*)d_in[0];  // [B,512]
    const float* w_prev     = (const float*)d_in[1];  // [B,128]
    const float* memory     = (const float*)d_in[2];  // [B,128,64]
    const float* W          = (const float*)d_in[3];  // [70,512]
    const float* bias       = (const float*)d_in[4];  // [70]

    const int B = in_sizes[1] / NN;   // 16384

    float* out_r = (float*)d_out;           // [B,64]
    float* out_w = out_r + (size_t)B * MM;  // [B,128]

    ntm_gemm_kernel<<<B / 64, 256>>>(embeddings, W, bias);
    ntm_addr_kernel<<<B, 128>>>(w_prev, memory, out_r, out_w);
}